// round 4
// baseline (speedup 1.0000x reference)
#include <cuda_runtime.h>
#include <cuda_fp16.h>

#define DD 160
#define HH 160
#define WW 160
#define NB 2
#define HW_ (HH * WW)
#define DHW_ (DD * HH * WW)          // 4,096,000
#define DHW2 (DHW_ / 2)
#define NVOX (NB * DHW_)             // 8,192,000
#define HCH 8
#define HL  (HH / HCH)               // 20
#define NPART (NB * 80 * HCH)        // 1280

// Gaussian weights for sigma = 7/6
#define G0c 0.0125602f
#define G1c 0.0788279f
#define G2c 0.2372961f
#define G3c 0.3426315f

typedef unsigned long long u64;

__device__ __forceinline__ u64 pk(float lo, float hi) {
    u64 r; asm("mov.b64 %0, {%1, %2};" : "=l"(r) : "f"(lo), "f"(hi)); return r;
}
__device__ __forceinline__ float2 upk(u64 v) {
    float2 r; asm("mov.b64 {%0, %1}, %2;" : "=f"(r.x), "=f"(r.y) : "l"(v)); return r;
}
__device__ __forceinline__ u64 fma2(u64 a, u64 b, u64 c) {
    u64 d; asm("fma.rn.f32x2 %0, %1, %2, %3;" : "=l"(d) : "l"(a), "l"(b), "l"(c)); return d;
}
__device__ __forceinline__ u64 mul2(u64 a, u64 b) {
    u64 d; asm("mul.rn.f32x2 %0, %1, %2;" : "=l"(d) : "l"(a), "l"(b)); return d;
}
__device__ __forceinline__ u64 add2(u64 a, u64 b) {
    u64 d; asm("add.rn.f32x2 %0, %1, %2;" : "=l"(d) : "l"(a), "l"(b)); return d;
}

// border valid-weight factor per axis (zero-padding mass correction)
__device__ __forceinline__ float bfac(int i) {
    float f = 1.f;
    if (i < 3)   f -= (i == 2 ? G0c : (i == 1 ? (G0c + G1c) : (G0c + G1c + G2c)));
    if (i > 156) f -= (i == 157 ? G0c : (i == 158 ? (G0c + G1c) : (G0c + G1c + G2c)));
    return f;
}

// fp16 scratch: 5 shifted conv-d fields x 2 batches (81.92 MB)
__device__ __half g_buf[10u * DHW_];
__device__ float g_partials[NPART];

// ---------------------------------------------------------------------------
// Pass 1: conv along D of {q, r, q^2, r^2, qr}, q=p-1/2, r=t-1/2.
// Thread owns a w-PAIR; all math packed f32x2; half2 stores.
// ---------------------------------------------------------------------------
__global__ void __launch_bounds__(128) pass1_kernel(const float* __restrict__ p,
                                                    const float* __restrict__ t,
                                                    int chunks, int L) {
    int tid = blockIdx.x * blockDim.x + threadIdx.x;
    const int ncol = NB * HH * 80;
    if (tid >= ncol * chunks) return;
    int col = tid % ncol;
    int ci  = tid / ncol;
    int d0  = ci * L;
    int wp  = col % 80;              // consecutive threads -> consecutive 8B
    int rem = col / 80;
    int h   = rem % HH;
    int n   = rem / HH;
    long base = (long)n * DHW_ + (long)h * WW + 2 * wp;   // float index

    const u64 Gp[4] = {pk(G0c,G0c), pk(G1c,G1c), pk(G2c,G2c), pk(G3c,G3c)};

    u64 win[5][7];
#pragma unroll
    for (int k = 0; k < 7; ++k) {
        int d = d0 - 3 + k;
        u64 q = 0, r = 0;
        if (d >= 0 && d < DD) {
            float2 a = *(const float2*)(p + base + (long)d * HW_);
            float2 b = *(const float2*)(t + base + (long)d * HW_);
            q = pk(a.x - 0.5f, a.y - 0.5f);
            r = pk(b.x - 0.5f, b.y - 0.5f);
        }
        win[0][k] = q; win[1][k] = r;
        win[2][k] = mul2(q, q); win[3][k] = mul2(r, r); win[4][k] = mul2(q, r);
    }

    __half2* ob2 = (__half2*)g_buf;
#pragma unroll 2
    for (int d = d0; d < d0 + L; ++d) {
        long ob = ((long)n * DHW_ + (long)d * HW_ + (long)h * WW) / 2 + wp;
#pragma unroll
        for (int f = 0; f < 5; ++f) {
            u64 acc = mul2(Gp[0], win[f][0]);
#pragma unroll
            for (int k = 1; k < 7; ++k)
                acc = fma2(Gp[k < 4 ? k : 6 - k], win[f][k], acc);
            float2 v = upk(acc);
            ob2[(long)(f * NB) * DHW2 + ob] = __floats2half2_rn(v.x, v.y);
        }
#pragma unroll
        for (int f = 0; f < 5; ++f)
#pragma unroll
            for (int k = 0; k < 6; ++k) win[f][k] = win[f][k + 1];
        int dn = d + 4;
        u64 q = 0, r = 0;
        if (dn < DD) {
            float2 a = *(const float2*)(p + base + (long)dn * HW_);
            float2 b = *(const float2*)(t + base + (long)dn * HW_);
            q = pk(a.x - 0.5f, a.y - 0.5f);
            r = pk(b.x - 0.5f, b.y - 0.5f);
        }
        win[0][6] = q; win[1][6] = r;
        win[2][6] = mul2(q, q); win[3][6] = mul2(r, r); win[4][6] = mul2(q, r);
    }
}

// ---------------------------------------------------------------------------
// Fused pass 2+3: block = (n, d-pair, h-chunk of 20). Threads: half = tid/80
// picks d-plane, lane = tid%80 owns w-pair (w2=2*lane). H-conv in packed
// registers; W-conv via dual-copy smem plane so all 7 taps are aligned LDS.64
// + FFMA2; exact border reconstruction; packed SSIM; in-block reduction.
//   copy A: A[x+4] = y[x]  (even-x pairs aligned)
//   copy B: B[x+3] = y[x]  (odd-x pairs aligned)
// ---------------------------------------------------------------------------
__global__ void __launch_bounds__(160) fused23_kernel() {
    __shared__ __align__(16) float plA[2][2][5][168];
    __shared__ __align__(16) float plB[2][2][5][168];
    __shared__ float sred[160];

    int bid  = blockIdx.x;
    int ch   = bid % HCH;
    int dp   = (bid / HCH) % 80;
    int n    = bid / (HCH * 80);
    int tid  = threadIdx.x;
    int half = tid / 80;
    int lane = tid % 80;
    int w2   = 2 * lane;
    int d    = 2 * dp + half;
    int h0   = ch * HL;

    const u64 G0p = pk(G0c,G0c), G1p = pk(G1c,G1c), G2p = pk(G2c,G2c), G3p = pk(G3c,G3c);
    const u64 K05 = pk(0.5f,0.5f), Kn025 = pk(-0.25f,-0.25f), K2 = pk(2.f,2.f);
    const u64 KC1 = pk(1e-4f,1e-4f), KC2 = pk(9e-4f,9e-4f), Kn1 = pk(-1.f,-1.f);

    // halo zeros (ends never rewritten)
    if (lane < 8) {
#pragma unroll
        for (int b = 0; b < 2; ++b)
#pragma unroll
            for (int f = 0; f < 5; ++f) {
                plA[b][half][f][lane] = 0.f;  plA[b][half][f][160 + lane] = 0.f;
                plB[b][half][f][lane] = 0.f;  plB[b][half][f][160 + lane] = 0.f;
            }
    }

    float bd = bfac(d);
    u64 wwp = pk(bd * bfac(w2), bd * bfac(w2 + 1));

    const __half2* ib2 = (const __half2*)g_buf;
    long base = ((long)d * HW_) / 2 + lane;   // + (f*NB+n)*DHW2 + row*80

    // prime 7-deep h-windows (packed)
    u64 win[5][7];
#pragma unroll
    for (int k = 0; k < 7; ++k) {
        int row = h0 - 3 + k;
        bool v = (row >= 0) && (row < HH);
        long off = base + (long)(v ? row : 0) * 80;
#pragma unroll
        for (int f = 0; f < 5; ++f) {
            if (v) {
                float2 fv = __half22float2(ib2[(long)(f * NB + n) * DHW2 + off]);
                win[f][k] = pk(fv.x, fv.y);
            } else win[f][k] = 0;
        }
    }
    __syncthreads();

    float acc_ssim = 0.f;

#pragma unroll 2
    for (int i = 0; i < HL; ++i) {
        int h = h0 + i;
        int buf = i & 1;

        // prefetch next row before the barrier
        int hn = h + 4;
        bool v = (hn < HH);
        long off = base + (long)(v ? hn : 0) * 80;
        u64 nxt[5];
#pragma unroll
        for (int f = 0; f < 5; ++f) {
            if (v) {
                float2 fv = __half22float2(ib2[(long)(f * NB + n) * DHW2 + off]);
                nxt[f] = pk(fv.x, fv.y);
            } else nxt[f] = 0;
        }

        // conv-h (packed) -> dual-copy smem plane
#pragma unroll
        for (int f = 0; f < 5; ++f) {
            u64 y = mul2(G0p, win[f][0]);
            y = fma2(G1p, win[f][1], y);
            y = fma2(G2p, win[f][2], y);
            y = fma2(G3p, win[f][3], y);
            y = fma2(G2p, win[f][4], y);
            y = fma2(G1p, win[f][5], y);
            y = fma2(G0p, win[f][6], y);
            *(u64*)&plA[buf][half][f][w2 + 4] = y;
            float2 yf = upk(y);
            plB[buf][half][f][w2 + 3] = yf.x;
            plB[buf][half][f][w2 + 4] = yf.y;
        }
        __syncthreads();

        // conv-w: 7 aligned LDS.64 + FFMA2 per field
        u64 c[5];
#pragma unroll
        for (int f = 0; f < 5; ++f) {
            const float* A = plA[buf][half][f];
            const float* B = plB[buf][half][f];
            u64 acc = mul2(G0p, *(const u64*)(B + w2));        // j=-3
            acc = fma2(G1p, *(const u64*)(A + w2 + 2), acc);   // j=-2
            acc = fma2(G2p, *(const u64*)(B + w2 + 2), acc);   // j=-1
            acc = fma2(G3p, *(const u64*)(A + w2 + 4), acc);   // j= 0
            acc = fma2(G2p, *(const u64*)(B + w2 + 4), acc);   // j=+1
            acc = fma2(G1p, *(const u64*)(A + w2 + 6), acc);   // j=+2
            acc = fma2(G0p, *(const u64*)(B + w2 + 6), acc);   // j=+3
            c[f] = acc;
        }

        // exact reconstruction + SSIM (packed)
        float bh = bfac(h);
        u64 W2  = mul2(wwp, pk(bh, bh));
        u64 mu1 = fma2(W2, K05, c[0]);
        u64 mu2 = fma2(W2, K05, c[1]);
        u64 Ep2 = fma2(W2, Kn025, add2(c[2], mu1));
        u64 Et2 = fma2(W2, Kn025, add2(c[3], mu2));
        u64 Ept = fma2(add2(mu1, mu2), K05, fma2(W2, Kn025, c[4]));
        u64 mu1s = mul2(mu1, mu1), mu2s = mul2(mu2, mu2), mu12 = mul2(mu1, mu2);
        u64 s1  = fma2(mu1s, Kn1, Ep2);
        u64 s2  = fma2(mu2s, Kn1, Et2);
        u64 s12 = fma2(mu12, Kn1, Ept);
        u64 num = mul2(fma2(mu12, K2, KC1), fma2(s12, K2, KC2));
        u64 den = mul2(add2(add2(mu1s, mu2s), KC1), add2(add2(s1, s2), KC2));
        float2 nf = upk(num), df = upk(den);
        acc_ssim += __fdividef(nf.x, df.x) + __fdividef(nf.y, df.y);

        // shift windows
#pragma unroll
        for (int f = 0; f < 5; ++f) {
#pragma unroll
            for (int k = 0; k < 6; ++k) win[f][k] = win[f][k + 1];
            win[f][6] = nxt[f];
        }
    }

    sred[tid] = acc_ssim;
    __syncthreads();
    for (int s = 128; s > 0; s >>= 1) {
        if (tid < s && tid + s < 160) sred[tid] += sred[tid + s];
        __syncthreads();
    }
    if (tid == 0) g_partials[bid] = sred[0];
}

// ---------------------------------------------------------------------------
// Final deterministic reduction of 1280 partials
// ---------------------------------------------------------------------------
__global__ void reduce_kernel(float* __restrict__ out) {
    __shared__ double sm[256];
    int tid = threadIdx.x;
    double acc = 0.0;
    for (int i = tid; i < NPART; i += 256) acc += (double)g_partials[i];
    sm[tid] = acc;
    __syncthreads();
    for (int s = 128; s > 0; s >>= 1) {
        if (tid < s) sm[tid] += sm[tid + s];
        __syncthreads();
    }
    if (tid == 0) out[0] = 1.f - (float)(sm[0] / (double)NVOX);
}

extern "C" void kernel_launch(void* const* d_in, const int* in_sizes, int n_in,
                              void* d_out, int out_size) {
    const float* p = (const float*)d_in[0];
    const float* t = (const float*)d_in[1];
    float* out = (float*)d_out;

    const int chunks = 4, L = DD / chunks;
    int th1 = NB * HH * 80 * chunks;                        // 102,400
    pass1_kernel<<<(th1 + 127) / 128, 128>>>(p, t, chunks, L);
    fused23_kernel<<<NB * 80 * HCH, 160>>>();               // 1280 blocks
    reduce_kernel<<<1, 256>>>(out);
}

// round 6
// speedup vs baseline: 1.5273x; 1.5273x over previous
#include <cuda_runtime.h>
#include <cuda_fp16.h>

#define DD 160
#define HH 160
#define WW 160
#define NB 2
#define HW_ (HH * WW)
#define DHW_ (DD * HH * WW)          // 4,096,000
#define DHW2 (DHW_ / 2)
#define NVOX (NB * DHW_)             // 8,192,000
#define DCH 4
#define DL  (DD / DCH)               // 40
#define HCH 5
#define HL  (HH / HCH)               // 32
#define NPART 500                    // passH blocks

#define G0c 0.0125602f
#define G1c 0.0788279f
#define G2c 0.2372961f
#define G3c 0.3426315f

typedef unsigned long long u64;

__device__ __forceinline__ float gk(int k) {
    constexpr float g[7] = {G0c, G1c, G2c, G3c, G2c, G1c, G0c};
    return g[k];
}
__device__ __forceinline__ u64 pk(float lo, float hi) {
    u64 r; asm("mov.b64 %0, {%1, %2};" : "=l"(r) : "f"(lo), "f"(hi)); return r;
}
__device__ __forceinline__ float2 upk(u64 v) {
    float2 r; asm("mov.b64 {%0, %1}, %2;" : "=f"(r.x), "=f"(r.y) : "l"(v)); return r;
}
__device__ __forceinline__ u64 fma2(u64 a, u64 b, u64 c) {
    u64 d; asm("fma.rn.f32x2 %0, %1, %2, %3;" : "=l"(d) : "l"(a), "l"(b), "l"(c)); return d;
}
__device__ __forceinline__ u64 mul2(u64 a, u64 b) {
    u64 d; asm("mul.rn.f32x2 %0, %1, %2;" : "=l"(d) : "l"(a), "l"(b)); return d;
}
__device__ __forceinline__ u64 add2(u64 a, u64 b) {
    u64 d; asm("add.rn.f32x2 %0, %1, %2;" : "=l"(d) : "l"(a), "l"(b)); return d;
}
__device__ __forceinline__ u64 h2f2(__half2 h) {
    float2 f = __half22float2(h); return pk(f.x, f.y);
}
__device__ __forceinline__ unsigned h2u(__half2 h) {
    return *reinterpret_cast<unsigned*>(&h);
}

// zero-padding valid-weight factor per axis
__device__ __forceinline__ float bfac(int i) {
    float f = 1.f;
    if (i < 3)   f -= (i == 2 ? G0c : (i == 1 ? (G0c + G1c) : (G0c + G1c + G2c)));
    if (i > 156) f -= (i == 157 ? G0c : (i == 158 ? (G0c + G1c) : (G0c + G1c + G2c)));
    return f;
}

// fp16 scratch: 5 shifted fields x 2 batches, two ping-pong buffers (164 MB)
__device__ __half g_buf[10u * DHW_];
__device__ __half g_buf2[10u * DHW_];
__device__ float g_partials[NPART];

// ---------------------------------------------------------------------------
// passW: 7-tap W-conv of the 5 shifted fields {q,r,q2,r2,qr}, q=p-1/2.
// Thread owns an 8-wide w-octet; 16-float neighborhood via 4+4 LDG.128;
// everything in registers; one STG.128 (8 halves) per field. No smem.
// Out-of-volume taps use field value 0 (exact: border corrected downstream
// by the analytic valid-mass W).
// ---------------------------------------------------------------------------
__global__ void __launch_bounds__(256) passW(const float* __restrict__ p,
                                             const float* __restrict__ t) {
    int tid = blockIdx.x * blockDim.x + threadIdx.x;   // 1,024,000
    int oct = tid % 20;
    int rem = tid / 20;
    int h   = rem % HH;
    int rm2 = rem / HH;
    int d   = rm2 % DD;
    int n   = rm2 / DD;
    int w0  = oct * 8;

    long rb = (long)n * DHW_ + ((long)d * HH + h) * WW + w0;
    const float4* p4 = (const float4*)(p + rb - 4);
    const float4* t4 = (const float4*)(t + rb - 4);
    const float4 z4 = {0.f, 0.f, 0.f, 0.f};

    float4 a0 = (oct > 0)  ? p4[0] : z4;
    float4 a1 = p4[1];
    float4 a2 = p4[2];
    float4 a3 = (oct < 19) ? p4[3] : z4;
    float4 b0 = (oct > 0)  ? t4[0] : z4;
    float4 b1 = t4[1];
    float4 b2 = t4[2];
    float4 b3 = (oct < 19) ? t4[3] : z4;

    float q[16], r[16];
    q[0]=a0.x-0.5f; q[1]=a0.y-0.5f; q[2]=a0.z-0.5f; q[3]=a0.w-0.5f;
    q[4]=a1.x-0.5f; q[5]=a1.y-0.5f; q[6]=a1.z-0.5f; q[7]=a1.w-0.5f;
    q[8]=a2.x-0.5f; q[9]=a2.y-0.5f; q[10]=a2.z-0.5f; q[11]=a2.w-0.5f;
    q[12]=a3.x-0.5f; q[13]=a3.y-0.5f; q[14]=a3.z-0.5f; q[15]=a3.w-0.5f;
    r[0]=b0.x-0.5f; r[1]=b0.y-0.5f; r[2]=b0.z-0.5f; r[3]=b0.w-0.5f;
    r[4]=b1.x-0.5f; r[5]=b1.y-0.5f; r[6]=b1.z-0.5f; r[7]=b1.w-0.5f;
    r[8]=b2.x-0.5f; r[9]=b2.y-0.5f; r[10]=b2.z-0.5f; r[11]=b2.w-0.5f;
    r[12]=b3.x-0.5f; r[13]=b3.y-0.5f; r[14]=b3.z-0.5f; r[15]=b3.w-0.5f;

    // force out-of-range field taps to exactly 0 (the -0.5 shift must not leak)
    if (oct == 0)  { q[0]=q[1]=q[2]=q[3]=0.f;     r[0]=r[1]=r[2]=r[3]=0.f; }
    if (oct == 19) { q[12]=q[13]=q[14]=q[15]=0.f; r[12]=r[13]=r[14]=r[15]=0.f; }

    float acc[5][8];
#pragma unroll
    for (int f = 0; f < 5; ++f)
#pragma unroll
        for (int j = 0; j < 8; ++j) acc[f][j] = 0.f;

#pragma unroll
    for (int k = 0; k < 7; ++k) {
#pragma unroll
        for (int j = 0; j < 8; ++j) {
            float qa = q[1 + j + k], ra = r[1 + j + k];
            float g = gk(k);
            acc[0][j] = fmaf(g, qa, acc[0][j]);
            acc[1][j] = fmaf(g, ra, acc[1][j]);
            acc[2][j] = fmaf(g * qa, qa, acc[2][j]);
            acc[3][j] = fmaf(g * ra, ra, acc[3][j]);
            acc[4][j] = fmaf(g * qa, ra, acc[4][j]);
        }
    }

    long ob = rb / 8;   // uint4 index (w0 multiple of 8 halves = 16B aligned)
    uint4* outv = (uint4*)g_buf;
#pragma unroll
    for (int f = 0; f < 5; ++f) {
        uint4 v;
        v.x = h2u(__floats2half2_rn(acc[f][0], acc[f][1]));
        v.y = h2u(__floats2half2_rn(acc[f][2], acc[f][3]));
        v.z = h2u(__floats2half2_rn(acc[f][4], acc[f][5]));
        v.w = h2u(__floats2half2_rn(acc[f][6], acc[f][7]));
        outv[(long)(f * NB) * (DHW_ / 8) + ob] = v;
    }
}

// ---------------------------------------------------------------------------
// passD: streaming 7-tap D-conv per field-volume. Thread = (vol,h,w-pair,
// d-chunk); rolling 7-register packed window; g_buf -> g_buf2. No smem.
// ---------------------------------------------------------------------------
__global__ void __launch_bounds__(256) passD() {
    int tid = blockIdx.x * blockDim.x + threadIdx.x;   // 512,000
    int wp  = tid % 80;
    int rem = tid / 80;
    int ci  = rem % DCH;
    int rm2 = rem / DCH;
    int h   = rm2 % HH;
    int vol = rm2 / HH;
    int d0  = ci * DL;

    const __half2* src = (const __half2*)g_buf  + (long)vol * DHW2 + (long)h * 80 + wp;
    __half2*       dst = (__half2*)g_buf2       + (long)vol * DHW2 + (long)h * 80 + wp;
    const int DS = HW_ / 2;   // 12800 half2 per d

    u64 win[7];
#pragma unroll
    for (int k = 0; k < 7; ++k) {
        int dd = d0 - 3 + k;
        win[k] = (dd >= 0 && dd < DD) ? h2f2(src[(long)dd * DS]) : 0;
    }

    const u64 G0p = pk(G0c,G0c), G1p = pk(G1c,G1c), G2p = pk(G2c,G2c), G3p = pk(G3c,G3c);
    const __half2* sp = src + (long)(d0 + 4) * DS;
    __half2*       dp = dst + (long)d0 * DS;

#pragma unroll 4
    for (int i = 0; i < DL; ++i) {
        int dn = d0 + i + 4;
        u64 nxt = (dn < DD) ? h2f2(*sp) : 0;
        u64 y = mul2(G0p, win[0]);
        y = fma2(G1p, win[1], y);
        y = fma2(G2p, win[2], y);
        y = fma2(G3p, win[3], y);
        y = fma2(G2p, win[4], y);
        y = fma2(G1p, win[5], y);
        y = fma2(G0p, win[6], y);
        float2 yf = upk(y);
        *dp = __floats2half2_rn(yf.x, yf.y);
#pragma unroll
        for (int k = 0; k < 6; ++k) win[k] = win[k + 1];
        win[6] = nxt;
        sp += DS; dp += DS;
    }
}

// ---------------------------------------------------------------------------
// passH: streaming 7-tap H-conv of 5 fields + exact border reconstruction +
// SSIM + per-thread accumulation + block reduction. No smem in hot loop.
// Thread = (n, d, w-pair, h-chunk of 32).
// ---------------------------------------------------------------------------
__global__ void __launch_bounds__(256) passH() {
    int tid = blockIdx.x * blockDim.x + threadIdx.x;   // 128,000
    int wp  = tid % 80;
    int rem = tid / 80;
    int ci  = rem % HCH;
    int rm2 = rem / HCH;
    int d   = rm2 % DD;
    int n   = rm2 / DD;
    int h0  = ci * HL;
    int w2  = 2 * wp;

    const u64 G0p = pk(G0c,G0c), G1p = pk(G1c,G1c), G2p = pk(G2c,G2c), G3p = pk(G3c,G3c);
    const u64 K05 = pk(0.5f,0.5f), Kn025 = pk(-0.25f,-0.25f), K2 = pk(2.f,2.f);
    const u64 KC1 = pk(1e-4f,1e-4f), KC2 = pk(9e-4f,9e-4f), Kn1 = pk(-1.f,-1.f);

    float bd = bfac(d);
    u64 wwp = pk(bd * bfac(w2), bd * bfac(w2 + 1));

    const __half2* base[5];
#pragma unroll
    for (int f = 0; f < 5; ++f)
        base[f] = (const __half2*)g_buf2 + (long)(f * NB + n) * DHW2 +
                  (long)d * (HW_ / 2) + wp;

    u64 win[5][7];
#pragma unroll
    for (int k = 0; k < 7; ++k) {
        int row = h0 - 3 + k;
        bool v = (row >= 0) && (row < HH);
        int ro = (v ? row : 0) * 80;
#pragma unroll
        for (int f = 0; f < 5; ++f)
            win[f][k] = v ? h2f2(base[f][ro]) : 0;
    }

    float acc_ssim = 0.f;
    int po = (h0 + 4) * 80;

#pragma unroll 4
    for (int i = 0; i < HL; ++i) {
        int h = h0 + i;
        int hn = h + 4;
        bool v = (hn < HH);
        u64 nxt[5];
#pragma unroll
        for (int f = 0; f < 5; ++f)
            nxt[f] = v ? h2f2(base[f][po]) : 0;

        u64 c[5];
#pragma unroll
        for (int f = 0; f < 5; ++f) {
            u64 y = mul2(G0p, win[f][0]);
            y = fma2(G1p, win[f][1], y);
            y = fma2(G2p, win[f][2], y);
            y = fma2(G3p, win[f][3], y);
            y = fma2(G2p, win[f][4], y);
            y = fma2(G1p, win[f][5], y);
            y = fma2(G0p, win[f][6], y);
            c[f] = y;
        }

        float bh = bfac(h);
        u64 W2  = mul2(wwp, pk(bh, bh));
        u64 mu1 = fma2(W2, K05, c[0]);
        u64 mu2 = fma2(W2, K05, c[1]);
        u64 Ep2 = fma2(W2, Kn025, add2(c[2], mu1));
        u64 Et2 = fma2(W2, Kn025, add2(c[3], mu2));
        u64 Ept = fma2(add2(mu1, mu2), K05, fma2(W2, Kn025, c[4]));
        u64 mu1s = mul2(mu1, mu1), mu2s = mul2(mu2, mu2), mu12 = mul2(mu1, mu2);
        u64 s1  = fma2(mu1s, Kn1, Ep2);
        u64 s2  = fma2(mu2s, Kn1, Et2);
        u64 s12 = fma2(mu12, Kn1, Ept);
        u64 num = mul2(fma2(mu12, K2, KC1), fma2(s12, K2, KC2));
        u64 den = mul2(add2(add2(mu1s, mu2s), KC1), add2(add2(s1, s2), KC2));
        float2 nf = upk(num), df = upk(den);
        acc_ssim += __fdividef(nf.x, df.x) + __fdividef(nf.y, df.y);

#pragma unroll
        for (int f = 0; f < 5; ++f) {
#pragma unroll
            for (int k = 0; k < 6; ++k) win[f][k] = win[f][k + 1];
            win[f][6] = nxt[f];
        }
        po += 80;
    }

    __shared__ float sred[256];
    int lt = threadIdx.x;
    sred[lt] = acc_ssim;
    __syncthreads();
    for (int s = 128; s > 0; s >>= 1) {
        if (lt < s) sred[lt] += sred[lt + s];
        __syncthreads();
    }
    if (lt == 0) g_partials[blockIdx.x] = sred[0];
}

// ---------------------------------------------------------------------------
// Final deterministic reduction of 500 partials
// ---------------------------------------------------------------------------
__global__ void reduce_kernel(float* __restrict__ out) {
    __shared__ double sm[256];
    int tid = threadIdx.x;
    double acc = 0.0;
    for (int i = tid; i < NPART; i += 256) acc += (double)g_partials[i];
    sm[tid] = acc;
    __syncthreads();
    for (int s = 128; s > 0; s >>= 1) {
        if (tid < s) sm[tid] += sm[tid + s];
        __syncthreads();
    }
    if (tid == 0) out[0] = 1.f - (float)(sm[0] / (double)NVOX);
}

extern "C" void kernel_launch(void* const* d_in, const int* in_sizes, int n_in,
                              void* d_out, int out_size) {
    const float* p = (const float*)d_in[0];
    const float* t = (const float*)d_in[1];
    float* out = (float*)d_out;

    passW<<<4000, 256>>>(p, t);     // 1,024,000 threads
    passD<<<2000, 256>>>();         //   512,000 threads
    passH<<<500, 256>>>();          //   128,000 threads
    reduce_kernel<<<1, 256>>>(out);
}